// round 9
// baseline (speedup 1.0000x reference)
#include <cuda_runtime.h>
#include <math_constants.h>
#include <cstdint>

// Problem constants (B=4, S=8, N=M=2048, D=3)
#define NSLICE 32             // B*S
#define NPTS   2048           // points per cloud
#define CHUNK  1024           // db points per block (smem tile)
#define NCHUNK (NPTS/CHUNK)   // 2
#define TPB    32             // threads per block (1 warp)
#define QPT    4              // queries per thread
#define QPB    (TPB*QPT)      // queries per block = 128
#define BPS    (NPTS/QPB)     // query-tiles per slice per direction = 16
#define NQTOT  (2*NSLICE*NPTS)  // total (dir,slice,query) = 131072
#define FA_BLOCKS 128

__device__ float g_vmin[NCHUNK][NQTOT];   // per-chunk per-query min of v
__device__ float g_partials[FA_BLOCKS];

// ---- packed f32x2 helpers (sm_103a; ptxas won't auto-fuse, must be PTX) ----
__device__ __forceinline__ unsigned long long fma2(unsigned long long a,
                                                   unsigned long long b,
                                                   unsigned long long c) {
    unsigned long long d;
    asm("fma.rn.f32x2 %0, %1, %2, %3;" : "=l"(d) : "l"(a), "l"(b), "l"(c));
    return d;
}
__device__ __forceinline__ unsigned long long bcast2(float v) {
    unsigned long long r;
    unsigned u = __float_as_uint(v);
    asm("mov.b64 %0, {%1, %2};" : "=l"(r) : "r"(u), "r"(u));
    return r;
}
__device__ __forceinline__ void min2(float& mlo, float& mhi, unsigned long long v) {
    unsigned lo, hi;
    asm("mov.b64 {%0, %1}, %2;" : "=r"(lo), "=r"(hi) : "l"(v));
    mlo = fminf(mlo, __uint_as_float(lo));
    mhi = fminf(mhi, __uint_as_float(hi));
}

// One block (1 warp): 128 query points (4/thread) vs ONE 1024-point chunk of
// the database of one slice+direction (2048 blocks total -> ~13.8 warps/SM).
// Writes per-query v-min for this chunk to g_vmin (no sqrt here).
// Per j-iter (4 db pts x 4 queries x 32 lanes = 512 pairs): 4 LDS.128 + 24 FFMA2 + 16 FMNMX.
__global__ __launch_bounds__(TPB) void chamfer_min_kernel(
    const float* __restrict__ pred,
    const float* __restrict__ target)
{
    __shared__ __align__(16) float s_x[CHUNK];
    __shared__ __align__(16) float s_y[CHUNK];
    __shared__ __align__(16) float s_z[CHUNK];
    __shared__ __align__(16) float s_c[CHUNK];

    const int tid   = threadIdx.x;
    const int slice = blockIdx.y;        // 0..31
    const int dir   = blockIdx.z >> 1;   // 0: pred->target, 1: target->pred
    const int chunk = blockIdx.z & 1;    // 0..1

    const float* __restrict__ qbase  = (dir == 0 ? pred   : target) + slice * NPTS * 3;
    const float* __restrict__ dbbase = (dir == 0 ? target : pred)   + slice * NPTS * 3
                                       + chunk * CHUNK * 3;

    // Four query points per thread
    const int q0 = blockIdx.x * QPB + tid;
    unsigned long long nqx[QPT], nqy[QPT], nqz[QPT];
    #pragma unroll
    for (int k = 0; k < QPT; ++k) {
        int q = q0 + k * TPB;
        nqx[k] = bcast2(-qbase[q * 3 + 0]);
        nqy[k] = bcast2(-qbase[q * 3 + 1]);
        nqz[k] = bcast2(-qbase[q * 3 + 2]);
    }

    // Fill db tile; c = 0.5*|t|^2
    #pragma unroll 4
    for (int j = tid; j < CHUNK; j += TPB) {
        float x = dbbase[j * 3 + 0];
        float y = dbbase[j * 3 + 1];
        float z = dbbase[j * 3 + 2];
        s_x[j] = x; s_y[j] = y; s_z[j] = z;
        s_c[j] = 0.5f * (x * x + y * y + z * z);
    }
    __syncwarp();

    // 2 independent min chains per query (8 total for ILP)
    float m0[QPT], m1[QPT];
    #pragma unroll
    for (int k = 0; k < QPT; ++k) { m0[k] = CUDART_INF_F; m1[k] = CUDART_INF_F; }

    const ulonglong2* __restrict__ xs = (const ulonglong2*)s_x;
    const ulonglong2* __restrict__ ys = (const ulonglong2*)s_y;
    const ulonglong2* __restrict__ zs = (const ulonglong2*)s_z;
    const ulonglong2* __restrict__ cs = (const ulonglong2*)s_c;

    #pragma unroll 4
    for (int j = 0; j < CHUNK / 4; ++j) {
        ulonglong2 xv = xs[j];   // (x0,x1),(x2,x3) packed f32x2
        ulonglong2 yv = ys[j];
        ulonglong2 zv = zs[j];
        ulonglong2 cv = cs[j];

        #pragma unroll
        for (int k = 0; k < QPT; ++k) {
            // v = c - q.t ; d^2 = |q|^2 + 2v (affine increasing => min v <=> min d)
            unsigned long long v01 =
                fma2(nqx[k], xv.x, fma2(nqy[k], yv.x, fma2(nqz[k], zv.x, cv.x)));
            unsigned long long v23 =
                fma2(nqx[k], xv.y, fma2(nqy[k], yv.y, fma2(nqz[k], zv.y, cv.y)));
            min2(m0[k], m1[k], v01);
            min2(m0[k], m1[k], v23);
        }
    }

    // Store per-query chunk min (sqrt deferred to the combine kernel)
    const int gq0 = dir * (NSLICE * NPTS) + slice * NPTS + q0;
    #pragma unroll
    for (int k = 0; k < QPT; ++k)
        g_vmin[chunk][gq0 + k * TPB] = fminf(m0[k], m1[k]);
}

// Combine the two chunk mins per query, apply sqrt, and sum into 128 block
// partials. Deterministic fixed-order per thread + warp butterflies.
__global__ __launch_bounds__(256) void chamfer_final_kernel(
    const float* __restrict__ pred,
    const float* __restrict__ target)
{
    __shared__ float red[8];
    const int tid = threadIdx.x;
    const int g0  = blockIdx.x * (NQTOT / FA_BLOCKS) + tid;  // 1024 queries/block

    float d = 0.0f;
    #pragma unroll
    for (int k = 0; k < 4; ++k) {
        int g = g0 + k * 256;
        float m = fminf(g_vmin[0][g], g_vmin[1][g]);
        int dir   = g >> 16;          // 65536 queries per direction
        int sq    = g & 0xFFFF;       // slice*2048 + q
        const float* p = (dir == 0 ? pred : target) + sq * 3;
        float qx = p[0], qy = p[1], qz = p[2];
        float q2 = qx * qx + qy * qy + qz * qz;
        d += sqrtf(fmaxf(fmaf(2.0f, m, q2), 0.0f));
    }

    #pragma unroll
    for (int s = 16; s > 0; s >>= 1)
        d += __shfl_xor_sync(0xFFFFFFFFu, d, s);
    if ((tid & 31) == 0) red[tid >> 5] = d;
    __syncthreads();
    if (tid == 0) {
        float t = red[0];
        #pragma unroll
        for (int w = 1; w < 8; ++w) t += red[w];
        g_partials[blockIdx.x] = t;
    }
}

// Final scalar: sum 128 partials, scale by 1/(B*S*N).
__global__ __launch_bounds__(128) void chamfer_reduce_kernel(float* __restrict__ out)
{
    __shared__ float red[4];
    const int tid = threadIdx.x;
    float s = g_partials[tid];
    #pragma unroll
    for (int sh = 16; sh > 0; sh >>= 1)
        s += __shfl_xor_sync(0xFFFFFFFFu, s, sh);
    if ((tid & 31) == 0) red[tid >> 5] = s;
    __syncthreads();
    if (tid == 0) {
        float t = red[0] + red[1] + red[2] + red[3];
        out[0] = t * (1.0f / 65536.0f);   // B*S*N = 32*2048
    }
}

extern "C" void kernel_launch(void* const* d_in, const int* in_sizes, int n_in,
                              void* d_out, int out_size)
{
    const float* pred   = (const float*)d_in[0];
    const float* target = (const float*)d_in[1];
    float* out = (float*)d_out;

    // 3 launches/call, main in slot 0: profiled global launch index 3
    // (3 mod 3 == 0) lands on chamfer_min_kernel.
    dim3 grid(BPS, NSLICE, 2 * NCHUNK);              // 16 x 32 x 4 = 2048 blocks
    chamfer_min_kernel<<<grid, TPB>>>(pred, target);  // slot 0 <- profiled
    chamfer_final_kernel<<<FA_BLOCKS, 256>>>(pred, target); // slot 1
    chamfer_reduce_kernel<<<1, 128>>>(out);           // slot 2
}

// round 11
// speedup vs baseline: 1.0397x; 1.0397x over previous
#include <cuda_runtime.h>
#include <math_constants.h>
#include <cstdint>

// Problem constants (B=4, S=8, N=M=2048, D=3)
#define NSLICE 32             // B*S
#define NPTS   2048           // points per cloud
#define CHUNK  512            // db points per block (smem tile)
#define NCHUNK (NPTS/CHUNK)   // 4
#define TPB    32             // threads per block (1 warp)
#define QPT    4              // queries per thread
#define QPB    (TPB*QPT)      // queries per block = 128
#define BPS    (NPTS/QPB)     // query-tiles per slice per direction = 16
#define NQTOT  (2*NSLICE*NPTS)  // total (dir,slice,query) = 131072
#define FA_BLOCKS 128

__device__ float g_vmin[NCHUNK][NQTOT];   // per-chunk per-query min of v
__device__ float g_partials[FA_BLOCKS];

// ---- packed f32x2 helpers (sm_103a; ptxas won't auto-fuse, must be PTX) ----
__device__ __forceinline__ unsigned long long fma2(unsigned long long a,
                                                   unsigned long long b,
                                                   unsigned long long c) {
    unsigned long long d;
    asm("fma.rn.f32x2 %0, %1, %2, %3;" : "=l"(d) : "l"(a), "l"(b), "l"(c));
    return d;
}
__device__ __forceinline__ unsigned long long bcast2(float v) {
    unsigned long long r;
    unsigned u = __float_as_uint(v);
    asm("mov.b64 %0, {%1, %2};" : "=l"(r) : "r"(u), "r"(u));
    return r;
}
__device__ __forceinline__ void min2(float& mlo, float& mhi, unsigned long long v) {
    unsigned lo, hi;
    asm("mov.b64 {%0, %1}, %2;" : "=r"(lo), "=r"(hi) : "l"(v));
    mlo = fminf(mlo, __uint_as_float(lo));
    mhi = fminf(mhi, __uint_as_float(hi));
}

// One block (1 warp): 128 query points (4/thread) vs ONE 512-point chunk of the
// database of one slice+direction. 4096 blocks -> ~27 warps/SM resident
// (regs capped at 85 via launch_bounds, smem 8.2 KB/block).
// Per j-iter (4 db pts x 4 queries x 32 lanes): 4 LDS.128 + 24 FFMA2 + 16 FMNMX.
__global__ __launch_bounds__(TPB, 24) void chamfer_min_kernel(
    const float* __restrict__ pred,
    const float* __restrict__ target)
{
    __shared__ __align__(16) float s_x[CHUNK];
    __shared__ __align__(16) float s_y[CHUNK];
    __shared__ __align__(16) float s_z[CHUNK];
    __shared__ __align__(16) float s_c[CHUNK];

    const int tid   = threadIdx.x;
    const int slice = blockIdx.y;          // 0..31
    const int dir   = blockIdx.z >> 2;     // 0: pred->target, 1: target->pred
    const int chunk = blockIdx.z & 3;      // 0..3

    const float* __restrict__ qbase  = (dir == 0 ? pred   : target) + slice * NPTS * 3;
    const float* __restrict__ dbbase = (dir == 0 ? target : pred)   + slice * NPTS * 3
                                       + chunk * CHUNK * 3;

    // Four query points per thread
    const int q0 = blockIdx.x * QPB + tid;
    unsigned long long nqx[QPT], nqy[QPT], nqz[QPT];
    #pragma unroll
    for (int k = 0; k < QPT; ++k) {
        int q = q0 + k * TPB;
        nqx[k] = bcast2(-qbase[q * 3 + 0]);
        nqy[k] = bcast2(-qbase[q * 3 + 1]);
        nqz[k] = bcast2(-qbase[q * 3 + 2]);
    }

    // Fill db tile; c = 0.5*|t|^2
    #pragma unroll 4
    for (int j = tid; j < CHUNK; j += TPB) {
        float x = dbbase[j * 3 + 0];
        float y = dbbase[j * 3 + 1];
        float z = dbbase[j * 3 + 2];
        s_x[j] = x; s_y[j] = y; s_z[j] = z;
        s_c[j] = 0.5f * (x * x + y * y + z * z);
    }
    __syncwarp();

    // 2 independent min chains per query (8 total for ILP)
    float m0[QPT], m1[QPT];
    #pragma unroll
    for (int k = 0; k < QPT; ++k) { m0[k] = CUDART_INF_F; m1[k] = CUDART_INF_F; }

    const ulonglong2* __restrict__ xs = (const ulonglong2*)s_x;
    const ulonglong2* __restrict__ ys = (const ulonglong2*)s_y;
    const ulonglong2* __restrict__ zs = (const ulonglong2*)s_z;
    const ulonglong2* __restrict__ cs = (const ulonglong2*)s_c;

    #pragma unroll 2
    for (int j = 0; j < CHUNK / 4; ++j) {
        ulonglong2 xv = xs[j];   // (x0,x1),(x2,x3) packed f32x2
        ulonglong2 yv = ys[j];
        ulonglong2 zv = zs[j];
        ulonglong2 cv = cs[j];

        #pragma unroll
        for (int k = 0; k < QPT; ++k) {
            // v = c - q.t ; d^2 = |q|^2 + 2v (affine increasing => min v <=> min d)
            unsigned long long v01 =
                fma2(nqx[k], xv.x, fma2(nqy[k], yv.x, fma2(nqz[k], zv.x, cv.x)));
            unsigned long long v23 =
                fma2(nqx[k], xv.y, fma2(nqy[k], yv.y, fma2(nqz[k], zv.y, cv.y)));
            min2(m0[k], m1[k], v01);
            min2(m0[k], m1[k], v23);
        }
    }

    // Store per-query chunk min (sqrt deferred to the combine kernel)
    const int gq0 = dir * (NSLICE * NPTS) + slice * NPTS + q0;
    #pragma unroll
    for (int k = 0; k < QPT; ++k)
        g_vmin[chunk][gq0 + k * TPB] = fminf(m0[k], m1[k]);
}

// Combine the four chunk mins per query, apply sqrt, and sum into 128 block
// partials. Deterministic fixed-order per thread + warp butterflies.
__global__ __launch_bounds__(256) void chamfer_final_kernel(
    const float* __restrict__ pred,
    const float* __restrict__ target)
{
    __shared__ float red[8];
    const int tid = threadIdx.x;
    const int g0  = blockIdx.x * (NQTOT / FA_BLOCKS) + tid;  // 1024 queries/block

    float d = 0.0f;
    #pragma unroll
    for (int k = 0; k < 4; ++k) {
        int g = g0 + k * 256;
        float m = fminf(fminf(g_vmin[0][g], g_vmin[1][g]),
                        fminf(g_vmin[2][g], g_vmin[3][g]));
        int dir   = g >> 16;          // 65536 queries per direction
        int sq    = g & 0xFFFF;       // slice*2048 + q
        const float* p = (dir == 0 ? pred : target) + sq * 3;
        float qx = p[0], qy = p[1], qz = p[2];
        float q2 = qx * qx + qy * qy + qz * qz;
        d += sqrtf(fmaxf(fmaf(2.0f, m, q2), 0.0f));
    }

    #pragma unroll
    for (int s = 16; s > 0; s >>= 1)
        d += __shfl_xor_sync(0xFFFFFFFFu, d, s);
    if ((tid & 31) == 0) red[tid >> 5] = d;
    __syncthreads();
    if (tid == 0) {
        float t = red[0];
        #pragma unroll
        for (int w = 1; w < 8; ++w) t += red[w];
        g_partials[blockIdx.x] = t;
    }
}

// Final scalar: sum 128 partials, scale by 1/(B*S*N).
__global__ __launch_bounds__(128) void chamfer_reduce_kernel(float* __restrict__ out)
{
    __shared__ float red[4];
    const int tid = threadIdx.x;
    float s = g_partials[tid];
    #pragma unroll
    for (int sh = 16; sh > 0; sh >>= 1)
        s += __shfl_xor_sync(0xFFFFFFFFu, s, sh);
    if ((tid & 31) == 0) red[tid >> 5] = s;
    __syncthreads();
    if (tid == 0) {
        float t = red[0] + red[1] + red[2] + red[3];
        out[0] = t * (1.0f / 65536.0f);   // B*S*N = 32*2048
    }
}

extern "C" void kernel_launch(void* const* d_in, const int* in_sizes, int n_in,
                              void* d_out, int out_size)
{
    const float* pred   = (const float*)d_in[0];
    const float* target = (const float*)d_in[1];
    float* out = (float*)d_out;

    // 3 launches/call, main in slot 0: profiled global launch index 3
    // (3 mod 3 == 0) lands on chamfer_min_kernel.
    dim3 grid(BPS, NSLICE, 2 * NCHUNK);               // 16 x 32 x 8 = 4096 blocks
    chamfer_min_kernel<<<grid, TPB>>>(pred, target);   // slot 0 <- profiled
    chamfer_final_kernel<<<FA_BLOCKS, 256>>>(pred, target); // slot 1
    chamfer_reduce_kernel<<<1, 128>>>(out);            // slot 2
}